// round 1
// baseline (speedup 1.0000x reference)
#include <cuda_runtime.h>
#include <math.h>

#define SQ   4096
#define NSEQ 80
#define CH   128
#define CH0  64

// ---------------- device scratch (sanctioned __device__ globals) ----------------
__device__ int   g_len[NSEQ];
__device__ float g_x[NSEQ * SQ * 3];
__device__ float g_h0[(size_t)NSEQ * SQ * CH0];
__device__ float g_bufA[(size_t)NSEQ * SQ * CH];
__device__ float g_bufB[(size_t)NSEQ * SQ * CH];
__device__ float g_skip[(size_t)NSEQ * SQ * CH];
__device__ float g_mean[NSEQ * CH];
__device__ float g_e[NSEQ * CH];
__device__ float g_feat[NSEQ * 2 * CH];
__device__ float g_cv1T[CH0 * CH];       // cv1_w transposed [k][o]
__device__ float g_rwT[3 * CH * CH];     // rs_rw transposed per stack [k][o]
__device__ float g_swT[3 * CH * CH];

// ---------------- helpers ----------------
__device__ __forceinline__ void mmtile(float a0, float a1, float a2, float a3,
                                       float4 b, float* acc) {
    acc[0]  = fmaf(a0, b.x, acc[0]);  acc[1]  = fmaf(a0, b.y, acc[1]);
    acc[2]  = fmaf(a0, b.z, acc[2]);  acc[3]  = fmaf(a0, b.w, acc[3]);
    acc[4]  = fmaf(a1, b.x, acc[4]);  acc[5]  = fmaf(a1, b.y, acc[5]);
    acc[6]  = fmaf(a1, b.z, acc[6]);  acc[7]  = fmaf(a1, b.w, acc[7]);
    acc[8]  = fmaf(a2, b.x, acc[8]);  acc[9]  = fmaf(a2, b.y, acc[9]);
    acc[10] = fmaf(a2, b.z, acc[10]); acc[11] = fmaf(a2, b.w, acc[11]);
    acc[12] = fmaf(a3, b.x, acc[12]); acc[13] = fmaf(a3, b.y, acc[13]);
    acc[14] = fmaf(a3, b.z, acc[14]); acc[15] = fmaf(a3, b.w, acc[15]);
}

__device__ __forceinline__ float sigmoidf(float x) { return 1.f / (1.f + expf(-x)); }

// ---------------- 1. stable gather per (batch, class) ----------------
__global__ void gather_kernel(const float* __restrict__ raw, const int* __restrict__ labels) {
    int seq = blockIdx.x;
    int b = seq / 10, cls = seq % 10 + 1;
    const int* lab = labels + b * SQ;
    __shared__ int cnt[256];
    __shared__ int scan[257];
    int t = threadIdx.x;
    int base = t * 16;
    int c = 0;
#pragma unroll
    for (int u = 0; u < 16; u++) c += (lab[base + u] == cls);
    cnt[t] = c;
    __syncthreads();
    if (t == 0) {
        int acc = 0;
        for (int i = 0; i < 256; i++) { scan[i] = acc; acc += cnt[i]; }
        scan[256] = acc;
        g_len[seq] = acc;
    }
    __syncthreads();
    int w = scan[t];
    const float* xb = raw + (size_t)b * SQ * 3;  // raw viewed as [B][S][3] (reshape)
    float* dst = g_x + (size_t)seq * SQ * 3;
    for (int u = 0; u < 16; u++) {
        int s = base + u;
        if (lab[s] == cls) {
            dst[w * 3 + 0] = xb[s * 3 + 0];
            dst[w * 3 + 1] = xb[s * 3 + 1];
            dst[w * 3 + 2] = xb[s * 3 + 2];
            w++;
        }
    }
}

// ---------------- prep: transpose small weight matrices ----------------
__global__ void prep_kernel(const float* __restrict__ cv1_w,
                            const float* __restrict__ rw, const float* __restrict__ sw) {
    int idx = blockIdx.x * 256 + threadIdx.x;
    if (idx < CH0 * CH) {
        int k = idx / CH, o = idx % CH;
        g_cv1T[idx] = cv1_w[o * CH0 + k];
    }
    for (int e = idx; e < 3 * CH * CH; e += gridDim.x * 256) {
        int st = e / (CH * CH);
        int r = e % (CH * CH);
        int k = r / CH, o = r % CH;
        g_rwT[e] = rw[(size_t)st * CH * CH + o * CH + k];
        g_swT[e] = sw[(size_t)st * CH * CH + o * CH + k];
    }
}

// ---------------- 2. cv0: relu(x3 @ W.T + b), K=3 ----------------
__global__ void cv0_kernel(const float* __restrict__ w, const float* __restrict__ b) {
    int seq = blockIdx.y;
    int L = g_len[seq];
    int j0 = blockIdx.x * 16;
    if (j0 >= L) return;
    __shared__ float ws[CH0 * 3];
    __shared__ float bs[CH0];
    if (threadIdx.x < CH0 * 3) ws[threadIdx.x] = w[threadIdx.x];
    if (threadIdx.x < CH0) bs[threadIdx.x] = b[threadIdx.x];
    __syncthreads();
    int j = j0 + (threadIdx.x >> 4);
    int c0 = (threadIdx.x & 15) * 4;
    if (j >= L) return;
    const float* xp = g_x + ((size_t)seq * SQ + j) * 3;
    float x0 = xp[0], x1 = xp[1], x2 = xp[2];
    float* out = g_h0 + ((size_t)seq * SQ + j) * CH0;
#pragma unroll
    for (int q = 0; q < 4; q++) {
        int c = c0 + q;
        float v = fmaf(x0, ws[c * 3 + 0], fmaf(x1, ws[c * 3 + 1], fmaf(x2, ws[c * 3 + 2], bs[c])));
        out[c] = fmaxf(v, 0.f);
    }
}

// ---------------- SE: masked mean over valid positions ----------------
__global__ void seavg_kernel(int which) {
    int seq = blockIdx.x, c = threadIdx.x;
    int L = g_len[seq];
    float s = 0.f;
    if (which == 0) {
        const float* p = g_h0 + (size_t)seq * SQ * CH0 + c;
        for (int j = 0; j < L; j++) s += p[(size_t)j * CH0];
    } else {
        const float* p = g_bufA + (size_t)seq * SQ * CH + c;
        for (int j = 0; j < L; j++) s += p[(size_t)j * CH];
    }
    g_mean[seq * CH + c] = s / fmaxf((float)L, 1.f);
}

// ---------------- SE: tiny MLP -> sigmoid gate ----------------
__global__ void semlp_kernel(const float* __restrict__ w1, const float* __restrict__ b1,
                             const float* __restrict__ w2, const float* __restrict__ b2,
                             int ch, int H) {
    int seq = blockIdx.x;
    int t = threadIdx.x;
    __shared__ float mn[CH];
    __shared__ float hid[8];
    mn[t] = g_mean[seq * CH + t];
    __syncthreads();
    if (t < H) {
        float a = b1[t];
        for (int k = 0; k < ch; k++) a = fmaf(mn[k], w1[t * ch + k], a);
        hid[t] = fmaxf(a, 0.f);
    }
    __syncthreads();
    float a = b2[t];
    for (int hh = 0; hh < H; hh++) a = fmaf(hid[hh], w2[t * H + hh], a);
    g_e[seq * CH + t] = sigmoidf(a);
}

// ---------------- 3. cv1 GEMM: relu((h0*e0) @ cv1_w.T + b), K=64 ----------------
__global__ void cv1_kernel(const float* __restrict__ cb) {
    int seq = blockIdx.y;
    int L = g_len[seq];
    int j0 = blockIdx.x * 32;
    if (j0 >= L) return;
    __shared__ __align__(16) float hs[32 * CH0];
    __shared__ __align__(16) float ws[CH0 * CH];
    const float* eb = g_e + seq * CH;
    for (int idx = threadIdx.x; idx < CH0 * CH; idx += 256)
        ws[idx] = g_cv1T[idx] * eb[idx >> 7];   // fold SE0 gate into weights
    const float* hp = g_h0 + (size_t)seq * SQ * CH0;
    for (int idx = threadIdx.x; idx < 32 * CH0; idx += 256) {
        int r = idx >> 6;
        int j = j0 + r;
        hs[idx] = (j < L) ? hp[(size_t)j * CH0 + (idx & 63)] : 0.f;
    }
    __syncthreads();
    int ty = threadIdx.x >> 5, tx = threadIdx.x & 31;
    float acc[16];
#pragma unroll
    for (int i = 0; i < 16; i++) acc[i] = 0.f;
#pragma unroll 4
    for (int k = 0; k < CH0; k++) {
        float a0 = hs[(ty * 4 + 0) * CH0 + k];
        float a1 = hs[(ty * 4 + 1) * CH0 + k];
        float a2 = hs[(ty * 4 + 2) * CH0 + k];
        float a3 = hs[(ty * 4 + 3) * CH0 + k];
        float4 bv = *(const float4*)&ws[k * CH + tx * 4];
        mmtile(a0, a1, a2, a3, bv, acc);
    }
    float* out = g_bufA + (size_t)seq * SQ * CH;
#pragma unroll
    for (int p = 0; p < 4; p++) {
        int j = j0 + ty * 4 + p;
        if (j < L) {
#pragma unroll
            for (int q = 0; q < 4; q++) {
                int c = tx * 4 + q;
                out[(size_t)j * CH + c] = fmaxf(acc[p * 4 + q] + cb[c], 0.f);
            }
        }
    }
}

// ---------------- apply SE1 gate in place ----------------
__global__ void scale_kernel() {
    int seq = blockIdx.y;
    int L = g_len[seq];
    int j = blockIdx.x * 8 + (threadIdx.x >> 5);
    if (j >= L) return;
    int c = (threadIdx.x & 31) * 4;
    float4* p = (float4*)(g_bufA + ((size_t)seq * SQ + j) * CH + c);
    const float4 e = *(const float4*)(g_e + seq * CH + c);
    float4 v = *p;
    v.x *= e.x; v.y *= e.y; v.z *= e.z; v.w *= e.w;
    *p = v;
}

// ---------------- 4. residual block: conv(K=3) GEMM + gate + res/skip GEMM ----------------
// im2col is free: A[j][kk] = hs[(j + kk/128)*128 + kk%128] = hs_flat[j*128 + kk]
__global__ void resblock_kernel(int flip,
                                const float* __restrict__ fw, const float* __restrict__ fb,
                                const float* __restrict__ gw, const float* __restrict__ gb,
                                const float* __restrict__ rb, const float* __restrict__ sb,
                                int stack, int skip_init) {
    int seq = blockIdx.y;
    int L = g_len[seq];
    int j0 = blockIdx.x * 32;
    if (j0 >= L) return;
    const float* hin = flip ? g_bufB : g_bufA;
    float* hout      = flip ? g_bufA : g_bufB;
    const float* rwT = g_rwT + (size_t)stack * CH * CH;
    const float* swT = g_swT + (size_t)stack * CH * CH;

    __shared__ __align__(16) float hs[34 * CH];   // rows j0-1 .. j0+32
    __shared__ __align__(16) float wa[16 * CH];
    __shared__ __align__(16) float wb[16 * CH];

    const float* hp = hin + (size_t)seq * SQ * CH;
    for (int idx = threadIdx.x; idx < 34 * CH; idx += 256) {
        int r = idx >> 7;
        int j = j0 - 1 + r;
        hs[idx] = (j >= 0 && j < L) ? hp[(size_t)j * CH + (idx & 127)] : 0.f;
    }
    __syncthreads();

    int ty = threadIdx.x >> 5, tx = threadIdx.x & 31;
    float fa[16], ga[16];
#pragma unroll
    for (int i = 0; i < 16; i++) { fa[i] = 0.f; ga[i] = 0.f; }

    // phase 1: f/g conv GEMM, K = 384
    for (int kc = 0; kc < 384; kc += 16) {
        const float4* fw4 = (const float4*)(fw + kc * CH);
        const float4* gw4 = (const float4*)(gw + kc * CH);
        float4* wa4 = (float4*)wa;
        float4* wb4 = (float4*)wb;
        for (int idx = threadIdx.x; idx < 512; idx += 256) {
            wa4[idx] = fw4[idx];
            wb4[idx] = gw4[idx];
        }
        __syncthreads();
#pragma unroll
        for (int k2 = 0; k2 < 16; k2++) {
            int kk = kc + k2;
            float a0 = hs[(ty * 4 + 0) * CH + kk];
            float a1 = hs[(ty * 4 + 1) * CH + kk];
            float a2 = hs[(ty * 4 + 2) * CH + kk];
            float a3 = hs[(ty * 4 + 3) * CH + kk];
            float4 bf = *(const float4*)&wa[k2 * CH + tx * 4];
            float4 bg = *(const float4*)&wb[k2 * CH + tx * 4];
            mmtile(a0, a1, a2, a3, bf, fa);
            mmtile(a0, a1, a2, a3, bg, ga);
        }
        __syncthreads();
    }

    // gated nonlinearity -> zg tile (alias onto hs; h re-read from global in epilogue)
    float* zgs = hs;
#pragma unroll
    for (int p = 0; p < 4; p++) {
#pragma unroll
        for (int q = 0; q < 4; q++) {
            int c = tx * 4 + q;
            float f = fa[p * 4 + q] + fb[c];
            float g = ga[p * 4 + q] + gb[c];
            zgs[(ty * 4 + p) * CH + c] = tanhf(f) * sigmoidf(g);
        }
    }
    __syncthreads();

    // phase 2: res/skip GEMM, K = 128
#pragma unroll
    for (int i = 0; i < 16; i++) { fa[i] = 0.f; ga[i] = 0.f; }
    for (int kc = 0; kc < CH; kc += 16) {
        const float4* rw4 = (const float4*)(rwT + kc * CH);
        const float4* sw4 = (const float4*)(swT + kc * CH);
        float4* wa4 = (float4*)wa;
        float4* wb4 = (float4*)wb;
        for (int idx = threadIdx.x; idx < 512; idx += 256) {
            wa4[idx] = rw4[idx];
            wb4[idx] = sw4[idx];
        }
        __syncthreads();
#pragma unroll
        for (int k2 = 0; k2 < 16; k2++) {
            int kk = kc + k2;
            float a0 = zgs[(ty * 4 + 0) * CH + kk];
            float a1 = zgs[(ty * 4 + 1) * CH + kk];
            float a2 = zgs[(ty * 4 + 2) * CH + kk];
            float a3 = zgs[(ty * 4 + 3) * CH + kk];
            float4 br = *(const float4*)&wa[k2 * CH + tx * 4];
            float4 bs = *(const float4*)&wb[k2 * CH + tx * 4];
            mmtile(a0, a1, a2, a3, br, fa);
            mmtile(a0, a1, a2, a3, bs, ga);
        }
        __syncthreads();
    }

    float* outr = hout + (size_t)seq * SQ * CH;
    float* outs = g_skip + (size_t)seq * SQ * CH;
#pragma unroll
    for (int p = 0; p < 4; p++) {
        int j = j0 + ty * 4 + p;
        if (j < L) {
#pragma unroll
            for (int q = 0; q < 4; q++) {
                int c = tx * 4 + q;
                float res = fa[p * 4 + q] + rb[c] + hp[(size_t)j * CH + c];
                outr[(size_t)j * CH + c] = res;
                float sk = ga[p * 4 + q] + sb[c];
                if (!skip_init) sk += outs[(size_t)j * CH + c];
                outs[(size_t)j * CH + c] = sk;
            }
        }
    }
}

// ---------------- 5. masked avg/max pool -> interleaved feat ----------------
__global__ void finalize_kernel(int flip) {
    int seq = blockIdx.x, c = threadIdx.x;
    int L = g_len[seq];
    const float* resv = flip ? g_bufA : g_bufB;   // final residual buffer
    const float* r = resv + (size_t)seq * SQ * CH + c;
    const float* s = g_skip + (size_t)seq * SQ * CH + c;
    float sum = 0.f, mx = -INFINITY;
    for (int j = 0; j < L; j++) {
        float v = r[(size_t)j * CH] + s[(size_t)j * CH];
        sum += v;
        mx = fmaxf(mx, v);
    }
    if (L == 0) mx = 0.f;
    float cnt = fmaxf((float)L, 1.f);
    g_feat[seq * 2 * CH + 2 * c]     = sum / cnt;
    g_feat[seq * 2 * CH + 2 * c + 1] = mx;
}

// ---------------- 6. head MLP: relu(feat @ l1.T + b1) @ l2.T + b2 ----------------
__global__ void head_kernel(const float* __restrict__ l1w, const float* __restrict__ l1b,
                            const float* __restrict__ l2w, const float* __restrict__ l2b,
                            float* __restrict__ out) {
    int seq = blockIdx.x, t = threadIdx.x;
    __shared__ float fs[256];
    __shared__ float r0[256], r1[256];
    fs[t] = g_feat[seq * 256 + t];
    __syncthreads();
    float o0 = 0.f, o1 = 0.f;
    for (int u = t; u < 1024; u += 256) {
        const float* w = l1w + (size_t)u * 256;
        float a = l1b[u];
#pragma unroll 8
        for (int v = 0; v < 256; v++) a = fmaf(fs[v], w[v], a);
        float hv = fmaxf(a, 0.f);
        o0 = fmaf(hv, l2w[u], o0);
        o1 = fmaf(hv, l2w[1024 + u], o1);
    }
    r0[t] = o0; r1[t] = o1;
    __syncthreads();
    for (int st = 128; st > 0; st >>= 1) {
        if (t < st) { r0[t] += r0[t + st]; r1[t] += r1[t + st]; }
        __syncthreads();
    }
    if (t == 0) {
        out[seq * 2 + 0] = r0[0] + l2b[0];
        out[seq * 2 + 1] = r1[0] + l2b[1];
    }
}

// ---------------- launch ----------------
extern "C" void kernel_launch(void* const* d_in, const int* in_sizes, int n_in,
                              void* d_out, int out_size) {
    const float* raw    = (const float*)d_in[0];
    const int*   labels = (const int*)  d_in[1];
    const float* cv0_w  = (const float*)d_in[2];
    const float* cv0_b  = (const float*)d_in[3];
    const float* se0_w1 = (const float*)d_in[4];
    const float* se0_b1 = (const float*)d_in[5];
    const float* se0_w2 = (const float*)d_in[6];
    const float* se0_b2 = (const float*)d_in[7];
    const float* cv1_w  = (const float*)d_in[8];
    const float* cv1_b  = (const float*)d_in[9];
    const float* se1_w1 = (const float*)d_in[10];
    const float* se1_b1 = (const float*)d_in[11];
    const float* se1_w2 = (const float*)d_in[12];
    const float* se1_b2 = (const float*)d_in[13];
    const float* rs_fw  = (const float*)d_in[14];
    const float* rs_fb  = (const float*)d_in[15];
    const float* rs_gw  = (const float*)d_in[16];
    const float* rs_gb  = (const float*)d_in[17];
    const float* rs_rw  = (const float*)d_in[18];   // transposed by prep_kernel
    const float* rs_rb  = (const float*)d_in[19];
    const float* rs_sw  = (const float*)d_in[20];
    const float* rs_sb  = (const float*)d_in[21];
    const float* l1_w   = (const float*)d_in[22];
    const float* l1_b   = (const float*)d_in[23];
    const float* l2_w   = (const float*)d_in[24];
    const float* l2_b   = (const float*)d_in[25];
    float* out = (float*)d_out;

    gather_kernel<<<NSEQ, 256>>>(raw, labels);
    prep_kernel<<<192, 256>>>(cv1_w, rs_rw, rs_sw);
    cv0_kernel<<<dim3(256, NSEQ), 256>>>(cv0_w, cv0_b);
    seavg_kernel<<<NSEQ, 64>>>(0);
    semlp_kernel<<<NSEQ, 64>>>(se0_w1, se0_b1, se0_w2, se0_b2, 64, 4);
    cv1_kernel<<<dim3(128, NSEQ), 256>>>(cv1_b);
    seavg_kernel<<<NSEQ, 128>>>(1);
    semlp_kernel<<<NSEQ, 128>>>(se1_w1, se1_b1, se1_w2, se1_b2, 128, 8);
    scale_kernel<<<dim3(512, NSEQ), 256>>>();

    for (int st = 0; st < 3; st++) {
        int flip = st & 1;  // 0: A->B, 1: B->A, 2: A->B
        resblock_kernel<<<dim3(128, NSEQ), 256>>>(
            flip,
            rs_fw + (size_t)st * 3 * CH * CH, rs_fb + st * CH,
            rs_gw + (size_t)st * 3 * CH * CH, rs_gb + st * CH,
            rs_rb + st * CH, rs_sb + st * CH,
            st, st == 0);
    }
    finalize_kernel<<<NSEQ, 128>>>(0 /* final res in g_bufB */);
    head_kernel<<<NSEQ, 256>>>(l1_w, l1_b, l2_w, l2_b, out);
}

// round 8
// speedup vs baseline: 1.0442x; 1.0442x over previous
#include <cuda_runtime.h>
#include <math.h>

#define SQ   4096
#define NSEQ 80
#define CH   128
#define CH0  64

// ---------------- device scratch ----------------
__device__ int   g_len[NSEQ];
__device__ float g_x[NSEQ * SQ * 3];
__device__ float g_h0[(size_t)NSEQ * SQ * CH0];
__device__ float g_bufA[(size_t)NSEQ * SQ * CH];
__device__ float g_bufB[(size_t)NSEQ * SQ * CH];
__device__ float g_skip[(size_t)NSEQ * SQ * CH];
__device__ float g_mean0[NSEQ * CH0];
__device__ float g_mean1[NSEQ * CH];
__device__ float g_e[NSEQ * CH];
__device__ float g_feat[NSEQ * 2 * CH];
__device__ float g_cv1T[CH0 * CH];       // cv1_w transposed [k][o]
__device__ float g_rwT[3 * CH * CH];     // rs_rw transposed per stack [k][o]
__device__ float g_swT[3 * CH * CH];

__device__ __forceinline__ float sigmoidf_(float x) { return 1.f / (1.f + expf(-x)); }

// ---------------- 1. stable gather per (batch, class) + zero mean buffers ----------------
__global__ void gather_kernel(const float* __restrict__ raw, const int* __restrict__ labels) {
    int seq = blockIdx.x;
    int b = seq / 10, cls = seq % 10 + 1;
    const int* lab = labels + b * SQ;
    __shared__ int cnt[256];
    __shared__ int scan[257];
    int t = threadIdx.x;
    if (t < CH0) g_mean0[seq * CH0 + t] = 0.f;
    if (t < CH)  g_mean1[seq * CH + t]  = 0.f;
    int base = t * 16;
    int c = 0;
#pragma unroll
    for (int u = 0; u < 16; u++) c += (lab[base + u] == cls);
    cnt[t] = c;
    __syncthreads();
    if (t == 0) {
        int acc = 0;
        for (int i = 0; i < 256; i++) { scan[i] = acc; acc += cnt[i]; }
        scan[256] = acc;
        g_len[seq] = acc;
    }
    __syncthreads();
    int w = scan[t];
    const float* xb = raw + (size_t)b * SQ * 3;
    float* dst = g_x + (size_t)seq * SQ * 3;
    for (int u = 0; u < 16; u++) {
        int s = base + u;
        if (lab[s] == cls) {
            dst[w * 3 + 0] = xb[s * 3 + 0];
            dst[w * 3 + 1] = xb[s * 3 + 1];
            dst[w * 3 + 2] = xb[s * 3 + 2];
            w++;
        }
    }
}

// ---------------- prep: transpose small weight matrices ----------------
__global__ void prep_kernel(const float* __restrict__ cv1_w,
                            const float* __restrict__ rw, const float* __restrict__ sw) {
    int idx = blockIdx.x * 256 + threadIdx.x;
    if (idx < CH0 * CH) {
        int k = idx / CH, o = idx % CH;
        g_cv1T[idx] = cv1_w[o * CH0 + k];
    }
    if (idx < 3 * CH * CH) {
        int st = idx / (CH * CH);
        int r = idx % (CH * CH);
        int k = r / CH, o = r % CH;
        g_rwT[idx] = rw[(size_t)st * CH * CH + o * CH + k];
        g_swT[idx] = sw[(size_t)st * CH * CH + o * CH + k];
    }
}

// ---------------- 2. cv0 (K=3) with fused SE0 mean partial-sums ----------------
__global__ void cv0_kernel(const float* __restrict__ w, const float* __restrict__ b) {
    int seq = blockIdx.y;
    int L = g_len[seq];
    int j0 = blockIdx.x * 16;
    if (j0 >= L) return;
    __shared__ float ws[CH0 * 3];
    __shared__ float bs[CH0];
    __shared__ float msum[CH0];
    int t = threadIdx.x;
    if (t < CH0 * 3) ws[t] = w[t];
    if (t < CH0) { bs[t] = b[t]; msum[t] = 0.f; }
    __syncthreads();
    int j = j0 + (t >> 4);
    int c0 = (t & 15) * 4;
    if (j < L) {
        const float* xp = g_x + ((size_t)seq * SQ + j) * 3;
        float x0 = xp[0], x1 = xp[1], x2 = xp[2];
        float* out = g_h0 + ((size_t)seq * SQ + j) * CH0;
        float v0 = fmaxf(fmaf(x0, ws[(c0+0)*3+0], fmaf(x1, ws[(c0+0)*3+1], fmaf(x2, ws[(c0+0)*3+2], bs[c0+0]))), 0.f);
        float v1 = fmaxf(fmaf(x0, ws[(c0+1)*3+0], fmaf(x1, ws[(c0+1)*3+1], fmaf(x2, ws[(c0+1)*3+2], bs[c0+1]))), 0.f);
        float v2 = fmaxf(fmaf(x0, ws[(c0+2)*3+0], fmaf(x1, ws[(c0+2)*3+1], fmaf(x2, ws[(c0+2)*3+2], bs[c0+2]))), 0.f);
        float v3 = fmaxf(fmaf(x0, ws[(c0+3)*3+0], fmaf(x1, ws[(c0+3)*3+1], fmaf(x2, ws[(c0+3)*3+2], bs[c0+3]))), 0.f);
        out[c0+0] = v0; out[c0+1] = v1; out[c0+2] = v2; out[c0+3] = v3;
        atomicAdd(&msum[c0+0], v0);
        atomicAdd(&msum[c0+1], v1);
        atomicAdd(&msum[c0+2], v2);
        atomicAdd(&msum[c0+3], v3);
    }
    __syncthreads();
    if (t < CH0) atomicAdd(&g_mean0[seq * CH0 + t], msum[t]);
}

// ---------------- SE MLP: partial sums -> mean -> sigmoid gate ----------------
// which: 0 -> g_mean0 (ch=64), 1 -> g_mean1 (ch=128). Selected in DEVICE code
// (passing a __device__ symbol as a kernel arg from host passes the host
// shadow address -> HMM faults -> 128MB device delta -> rule violation).
__global__ void semlp_kernel(int which,
                             const float* __restrict__ w1, const float* __restrict__ b1,
                             const float* __restrict__ w2, const float* __restrict__ b2,
                             int ch, int H) {
    int seq = blockIdx.x;
    int t = threadIdx.x;
    __shared__ float mn[CH];
    __shared__ float hid[8];
    const float* sums = which ? g_mean1 : g_mean0;
    float inv = 1.f / fmaxf((float)g_len[seq], 1.f);
    mn[t] = sums[seq * ch + t] * inv;
    __syncthreads();
    if (t < H) {
        float a = b1[t];
        for (int k = 0; k < ch; k++) a = fmaf(mn[k], w1[t * ch + k], a);
        hid[t] = fmaxf(a, 0.f);
    }
    __syncthreads();
    float a = b2[t];
    for (int hh = 0; hh < H; hh++) a = fmaf(hid[hh], w2[t * H + hh], a);
    g_e[seq * CH + t] = sigmoidf_(a);
}

// ---------------- 3. cv1 GEMM (SE0 folded into weights) + fused SE1 mean sums ----------------
__global__ void cv1_kernel(const float* __restrict__ cb) {
    int seq = blockIdx.y;
    int L = g_len[seq];
    int j0 = blockIdx.x * 32;
    if (j0 >= L) return;
    __shared__ __align__(16) float hs[32 * CH0];
    __shared__ __align__(16) float ws[CH0 * CH];
    __shared__ float sred[8 * CH];
    const float* eb = g_e + seq * CH;
    for (int idx = threadIdx.x; idx < CH0 * CH; idx += 256)
        ws[idx] = g_cv1T[idx] * eb[idx >> 7];   // fold SE0 gate
    const float* hp = g_h0 + (size_t)seq * SQ * CH0;
    for (int idx = threadIdx.x; idx < 32 * CH0; idx += 256) {
        int r = idx >> 6;
        int j = j0 + r;
        hs[idx] = (j < L) ? hp[(size_t)j * CH0 + (idx & 63)] : 0.f;
    }
    __syncthreads();
    int ty = threadIdx.x >> 5, tx = threadIdx.x & 31;
    float acc[16];
#pragma unroll
    for (int i = 0; i < 16; i++) acc[i] = 0.f;
#pragma unroll 4
    for (int k = 0; k < CH0; k++) {
        float a0 = hs[(ty * 4 + 0) * CH0 + k];
        float a1 = hs[(ty * 4 + 1) * CH0 + k];
        float a2 = hs[(ty * 4 + 2) * CH0 + k];
        float a3 = hs[(ty * 4 + 3) * CH0 + k];
        float4 bv = *(const float4*)&ws[k * CH + tx * 4];
        acc[0]  = fmaf(a0, bv.x, acc[0]);  acc[1]  = fmaf(a0, bv.y, acc[1]);
        acc[2]  = fmaf(a0, bv.z, acc[2]);  acc[3]  = fmaf(a0, bv.w, acc[3]);
        acc[4]  = fmaf(a1, bv.x, acc[4]);  acc[5]  = fmaf(a1, bv.y, acc[5]);
        acc[6]  = fmaf(a1, bv.z, acc[6]);  acc[7]  = fmaf(a1, bv.w, acc[7]);
        acc[8]  = fmaf(a2, bv.x, acc[8]);  acc[9]  = fmaf(a2, bv.y, acc[9]);
        acc[10] = fmaf(a2, bv.z, acc[10]); acc[11] = fmaf(a2, bv.w, acc[11]);
        acc[12] = fmaf(a3, bv.x, acc[12]); acc[13] = fmaf(a3, bv.y, acc[13]);
        acc[14] = fmaf(a3, bv.z, acc[14]); acc[15] = fmaf(a3, bv.w, acc[15]);
    }
    float* out = g_bufA + (size_t)seq * SQ * CH;
    float cs0 = 0.f, cs1 = 0.f, cs2 = 0.f, cs3 = 0.f;
#pragma unroll
    for (int p = 0; p < 4; p++) {
        int j = j0 + ty * 4 + p;
        if (j < L) {
            int c = tx * 4;
            float v0 = fmaxf(acc[p * 4 + 0] + cb[c + 0], 0.f);
            float v1 = fmaxf(acc[p * 4 + 1] + cb[c + 1], 0.f);
            float v2 = fmaxf(acc[p * 4 + 2] + cb[c + 2], 0.f);
            float v3 = fmaxf(acc[p * 4 + 3] + cb[c + 3], 0.f);
            out[(size_t)j * CH + c + 0] = v0;
            out[(size_t)j * CH + c + 1] = v1;
            out[(size_t)j * CH + c + 2] = v2;
            out[(size_t)j * CH + c + 3] = v3;
            cs0 += v0; cs1 += v1; cs2 += v2; cs3 += v3;
        }
    }
    sred[ty * CH + tx * 4 + 0] = cs0;
    sred[ty * CH + tx * 4 + 1] = cs1;
    sred[ty * CH + tx * 4 + 2] = cs2;
    sred[ty * CH + tx * 4 + 3] = cs3;
    __syncthreads();
    if (threadIdx.x < CH) {
        float s = 0.f;
#pragma unroll
        for (int w = 0; w < 8; w++) s += sred[w * CH + threadIdx.x];
        atomicAdd(&g_mean1[seq * CH + threadIdx.x], s);
    }
}

// ---------------- 4. residual block (R1-proven body) + SE1 fold + last-stack fusion ----------
// im2col is free: A[j][kk] = hs_flat[j*128 + kk], kk in [0,384)
__global__ void resblock_kernel(int flip,
                                const float* __restrict__ fw, const float* __restrict__ fb,
                                const float* __restrict__ gw, const float* __restrict__ gb,
                                const float* __restrict__ rb, const float* __restrict__ sb,
                                int stack, int skip_init, int applyE, int last) {
    int seq = blockIdx.y;
    int L = g_len[seq];
    int j0 = blockIdx.x * 32;
    if (j0 >= L) return;
    const float* hin = flip ? g_bufB : g_bufA;
    float* hout      = flip ? g_bufA : g_bufB;
    const float* rwT = g_rwT + (size_t)stack * CH * CH;
    const float* swT = g_swT + (size_t)stack * CH * CH;

    __shared__ __align__(16) float hs[34 * CH];   // rows j0-1 .. j0+32
    __shared__ __align__(16) float wa[16 * CH];
    __shared__ __align__(16) float wb[16 * CH];
    __shared__ float es[CH];

    int t = threadIdx.x;
    if (t < CH) es[t] = applyE ? g_e[seq * CH + t] : 1.f;
    __syncthreads();

    const float* hp = hin + (size_t)seq * SQ * CH;
    for (int idx = t; idx < 34 * CH; idx += 256) {
        int r = idx >> 7;
        int j = j0 - 1 + r;
        float v = (j >= 0 && j < L) ? hp[(size_t)j * CH + (idx & 127)] : 0.f;
        hs[idx] = v * es[idx & 127];
    }
    __syncthreads();

    int ty = t >> 5, tx = t & 31;
    float fa[16], ga[16];
#pragma unroll
    for (int i = 0; i < 16; i++) { fa[i] = 0.f; ga[i] = 0.f; }

    // phase 1: f/g conv GEMM, K = 384
    for (int kc = 0; kc < 384; kc += 16) {
        const float4* fw4 = (const float4*)(fw + kc * CH);
        const float4* gw4 = (const float4*)(gw + kc * CH);
        float4* wa4 = (float4*)wa;
        float4* wb4 = (float4*)wb;
        for (int idx = t; idx < 512; idx += 256) {
            wa4[idx] = fw4[idx];
            wb4[idx] = gw4[idx];
        }
        __syncthreads();
#pragma unroll
        for (int k2 = 0; k2 < 16; k2++) {
            int kk = kc + k2;
            float a0 = hs[(ty * 4 + 0) * CH + kk];
            float a1 = hs[(ty * 4 + 1) * CH + kk];
            float a2 = hs[(ty * 4 + 2) * CH + kk];
            float a3 = hs[(ty * 4 + 3) * CH + kk];
            float4 bf = *(const float4*)&wa[k2 * CH + tx * 4];
            float4 bg = *(const float4*)&wb[k2 * CH + tx * 4];
            fa[0]  = fmaf(a0, bf.x, fa[0]);  fa[1]  = fmaf(a0, bf.y, fa[1]);
            fa[2]  = fmaf(a0, bf.z, fa[2]);  fa[3]  = fmaf(a0, bf.w, fa[3]);
            fa[4]  = fmaf(a1, bf.x, fa[4]);  fa[5]  = fmaf(a1, bf.y, fa[5]);
            fa[6]  = fmaf(a1, bf.z, fa[6]);  fa[7]  = fmaf(a1, bf.w, fa[7]);
            fa[8]  = fmaf(a2, bf.x, fa[8]);  fa[9]  = fmaf(a2, bf.y, fa[9]);
            fa[10] = fmaf(a2, bf.z, fa[10]); fa[11] = fmaf(a2, bf.w, fa[11]);
            fa[12] = fmaf(a3, bf.x, fa[12]); fa[13] = fmaf(a3, bf.y, fa[13]);
            fa[14] = fmaf(a3, bf.z, fa[14]); fa[15] = fmaf(a3, bf.w, fa[15]);
            ga[0]  = fmaf(a0, bg.x, ga[0]);  ga[1]  = fmaf(a0, bg.y, ga[1]);
            ga[2]  = fmaf(a0, bg.z, ga[2]);  ga[3]  = fmaf(a0, bg.w, ga[3]);
            ga[4]  = fmaf(a1, bg.x, ga[4]);  ga[5]  = fmaf(a1, bg.y, ga[5]);
            ga[6]  = fmaf(a1, bg.z, ga[6]);  ga[7]  = fmaf(a1, bg.w, ga[7]);
            ga[8]  = fmaf(a2, bg.x, ga[8]);  ga[9]  = fmaf(a2, bg.y, ga[9]);
            ga[10] = fmaf(a2, bg.z, ga[10]); ga[11] = fmaf(a2, bg.w, ga[11]);
            ga[12] = fmaf(a3, bg.x, ga[12]); ga[13] = fmaf(a3, bg.y, ga[13]);
            ga[14] = fmaf(a3, bg.z, ga[14]); ga[15] = fmaf(a3, bg.w, ga[15]);
        }
        __syncthreads();
    }

    // gated nonlinearity -> zg tile (alias onto hs rows 0..31)
    float* zgs = hs;
#pragma unroll
    for (int p = 0; p < 4; p++) {
#pragma unroll
        for (int q = 0; q < 4; q++) {
            int c = tx * 4 + q;
            float f = fa[p * 4 + q] + fb[c];
            float g = ga[p * 4 + q] + gb[c];
            zgs[(ty * 4 + p) * CH + c] = tanhf(f) * sigmoidf_(g);
        }
    }
    __syncthreads();

    // phase 2: res/skip GEMM, K = 128
#pragma unroll
    for (int i = 0; i < 16; i++) { fa[i] = 0.f; ga[i] = 0.f; }
    for (int kc = 0; kc < CH; kc += 16) {
        const float4* rw4 = (const float4*)(rwT + kc * CH);
        const float4* sw4 = (const float4*)(swT + kc * CH);
        float4* wa4 = (float4*)wa;
        float4* wb4 = (float4*)wb;
        for (int idx = t; idx < 512; idx += 256) {
            wa4[idx] = rw4[idx];
            wb4[idx] = sw4[idx];
        }
        __syncthreads();
#pragma unroll
        for (int k2 = 0; k2 < 16; k2++) {
            int kk = kc + k2;
            float a0 = zgs[(ty * 4 + 0) * CH + kk];
            float a1 = zgs[(ty * 4 + 1) * CH + kk];
            float a2 = zgs[(ty * 4 + 2) * CH + kk];
            float a3 = zgs[(ty * 4 + 3) * CH + kk];
            float4 br = *(const float4*)&wa[k2 * CH + tx * 4];
            float4 bs = *(const float4*)&wb[k2 * CH + tx * 4];
            fa[0]  = fmaf(a0, br.x, fa[0]);  fa[1]  = fmaf(a0, br.y, fa[1]);
            fa[2]  = fmaf(a0, br.z, fa[2]);  fa[3]  = fmaf(a0, br.w, fa[3]);
            fa[4]  = fmaf(a1, br.x, fa[4]);  fa[5]  = fmaf(a1, br.y, fa[5]);
            fa[6]  = fmaf(a1, br.z, fa[6]);  fa[7]  = fmaf(a1, br.w, fa[7]);
            fa[8]  = fmaf(a2, br.x, fa[8]);  fa[9]  = fmaf(a2, br.y, fa[9]);
            fa[10] = fmaf(a2, br.z, fa[10]); fa[11] = fmaf(a2, br.w, fa[11]);
            fa[12] = fmaf(a3, br.x, fa[12]); fa[13] = fmaf(a3, br.y, fa[13]);
            fa[14] = fmaf(a3, br.z, fa[14]); fa[15] = fmaf(a3, br.w, fa[15]);
            ga[0]  = fmaf(a0, bs.x, ga[0]);  ga[1]  = fmaf(a0, bs.y, ga[1]);
            ga[2]  = fmaf(a0, bs.z, ga[2]);  ga[3]  = fmaf(a0, bs.w, ga[3]);
            ga[4]  = fmaf(a1, bs.x, ga[4]);  ga[5]  = fmaf(a1, bs.y, ga[5]);
            ga[6]  = fmaf(a1, bs.z, ga[6]);  ga[7]  = fmaf(a1, bs.w, ga[7]);
            ga[8]  = fmaf(a2, bs.x, ga[8]);  ga[9]  = fmaf(a2, bs.y, ga[9]);
            ga[10] = fmaf(a2, bs.z, ga[10]); ga[11] = fmaf(a2, bs.w, ga[11]);
            ga[12] = fmaf(a3, bs.x, ga[12]); ga[13] = fmaf(a3, bs.y, ga[13]);
            ga[14] = fmaf(a3, bs.z, ga[14]); ga[15] = fmaf(a3, bs.w, ga[15]);
        }
        __syncthreads();
    }

    float* outr = hout + (size_t)seq * SQ * CH;
    float* outs = g_skip + (size_t)seq * SQ * CH;
#pragma unroll
    for (int p = 0; p < 4; p++) {
        int j = j0 + ty * 4 + p;
        if (j < L) {
#pragma unroll
            for (int q = 0; q < 4; q++) {
                int c = tx * 4 + q;
                float res = fa[p * 4 + q] + rb[c] + hp[(size_t)j * CH + c] * es[c];
                float sk = ga[p * 4 + q] + sb[c];
                if (!skip_init) sk += outs[(size_t)j * CH + c];
                if (last) {
                    outs[(size_t)j * CH + c] = res + sk;   // fused final res+skip
                } else {
                    outr[(size_t)j * CH + c] = res;
                    outs[(size_t)j * CH + c] = sk;
                }
            }
        }
    }
}

// ---------------- 5. masked avg/max pool (reads fused res+skip from g_skip) ----------------
__global__ void finalize_kernel() {
    int seq = blockIdx.x;
    int L = g_len[seq];
    int t = threadIdx.x;
    int c = t & 127, half = t >> 7;
    const float* s = g_skip + (size_t)seq * SQ * CH + c;
    float sum = 0.f, mx = -INFINITY;
    for (int j = half; j < L; j += 2) {
        float v = s[(size_t)j * CH];
        sum += v;
        mx = fmaxf(mx, v);
    }
    __shared__ float ssum[256], smx[256];
    ssum[t] = sum; smx[t] = mx;
    __syncthreads();
    if (t < 128) {
        float su = ssum[t] + ssum[t + 128];
        float m = fmaxf(smx[t], smx[t + 128]);
        if (L == 0) m = 0.f;
        float cnt = fmaxf((float)L, 1.f);
        g_feat[seq * 2 * CH + 2 * t]     = su / cnt;
        g_feat[seq * 2 * CH + 2 * t + 1] = m;
    }
}

// ---------------- 6. head MLP ----------------
__global__ void head_kernel(const float* __restrict__ l1w, const float* __restrict__ l1b,
                            const float* __restrict__ l2w, const float* __restrict__ l2b,
                            float* __restrict__ out) {
    int seq = blockIdx.x, t = threadIdx.x;
    __shared__ float fs[256];
    __shared__ float r0[256], r1[256];
    fs[t] = g_feat[seq * 256 + t];
    __syncthreads();
    float o0 = 0.f, o1 = 0.f;
    for (int u = t; u < 1024; u += 256) {
        const float* w = l1w + (size_t)u * 256;
        float a = l1b[u];
#pragma unroll 8
        for (int v = 0; v < 256; v++) a = fmaf(fs[v], w[v], a);
        float hv = fmaxf(a, 0.f);
        o0 = fmaf(hv, l2w[u], o0);
        o1 = fmaf(hv, l2w[1024 + u], o1);
    }
    r0[t] = o0; r1[t] = o1;
    __syncthreads();
    for (int st = 128; st > 0; st >>= 1) {
        if (t < st) { r0[t] += r0[t + st]; r1[t] += r1[t + st]; }
        __syncthreads();
    }
    if (t == 0) {
        out[seq * 2 + 0] = r0[0] + l2b[0];
        out[seq * 2 + 1] = r1[0] + l2b[1];
    }
}

// ---------------- launch ----------------
extern "C" void kernel_launch(void* const* d_in, const int* in_sizes, int n_in,
                              void* d_out, int out_size) {
    const float* raw    = (const float*)d_in[0];
    const int*   labels = (const int*)  d_in[1];
    const float* cv0_w  = (const float*)d_in[2];
    const float* cv0_b  = (const float*)d_in[3];
    const float* se0_w1 = (const float*)d_in[4];
    const float* se0_b1 = (const float*)d_in[5];
    const float* se0_w2 = (const float*)d_in[6];
    const float* se0_b2 = (const float*)d_in[7];
    const float* cv1_w  = (const float*)d_in[8];
    const float* cv1_b  = (const float*)d_in[9];
    const float* se1_w1 = (const float*)d_in[10];
    const float* se1_b1 = (const float*)d_in[11];
    const float* se1_w2 = (const float*)d_in[12];
    const float* se1_b2 = (const float*)d_in[13];
    const float* rs_fw  = (const float*)d_in[14];
    const float* rs_fb  = (const float*)d_in[15];
    const float* rs_gw  = (const float*)d_in[16];
    const float* rs_gb  = (const float*)d_in[17];
    const float* rs_rw  = (const float*)d_in[18];
    const float* rs_rb  = (const float*)d_in[19];
    const float* rs_sw  = (const float*)d_in[20];
    const float* rs_sb  = (const float*)d_in[21];
    const float* l1_w   = (const float*)d_in[22];
    const float* l1_b   = (const float*)d_in[23];
    const float* l2_w   = (const float*)d_in[24];
    const float* l2_b   = (const float*)d_in[25];
    float* out = (float*)d_out;

    gather_kernel<<<NSEQ, 256>>>(raw, labels);
    prep_kernel<<<192, 256>>>(cv1_w, rs_rw, rs_sw);
    cv0_kernel<<<dim3(256, NSEQ), 256>>>(cv0_w, cv0_b);
    semlp_kernel<<<NSEQ, 64>>>(0, se0_w1, se0_b1, se0_w2, se0_b2, 64, 4);
    cv1_kernel<<<dim3(128, NSEQ), 256>>>(cv1_b);
    semlp_kernel<<<NSEQ, 128>>>(1, se1_w1, se1_b1, se1_w2, se1_b2, 128, 8);

    for (int st = 0; st < 3; st++) {
        int flip = st & 1;  // 0: A->B, 1: B->A, 2: A->(fused into g_skip)
        resblock_kernel<<<dim3(128, NSEQ), 256>>>(
            flip,
            rs_fw + (size_t)st * 3 * CH * CH, rs_fb + st * CH,
            rs_gw + (size_t)st * 3 * CH * CH, rs_gb + st * CH,
            rs_rb + st * CH, rs_sb + st * CH,
            st, st == 0, st == 0, st == 2);
    }
    finalize_kernel<<<NSEQ, 256>>>();
    head_kernel<<<NSEQ, 256>>>(l1_w, l1_b, l2_w, l2_b, out);
}

// round 9
// speedup vs baseline: 1.2749x; 1.2209x over previous
#include <cuda_runtime.h>
#include <cstdint>
#include <math.h>

#define SQ   4096
#define NSEQ 80
#define CH   128
#define CH0  64

// ---------------- device scratch ----------------
__device__ int   g_len[NSEQ];
__device__ float g_x[NSEQ * SQ * 3];
__device__ float g_h0[(size_t)NSEQ * SQ * CH0];
__device__ float g_bufA[(size_t)NSEQ * SQ * CH];
__device__ float g_bufB[(size_t)NSEQ * SQ * CH];
__device__ float g_skip[(size_t)NSEQ * SQ * CH];
__device__ float g_mean0[NSEQ * CH0];
__device__ float g_mean1[NSEQ * CH];
__device__ float g_e[NSEQ * CH];
__device__ float g_feat[NSEQ * 2 * CH];
__device__ float g_cv1T[CH0 * CH];       // cv1_w transposed [k][o]
__device__ float g_rwT[3 * CH * CH];     // rs_rw transposed per stack [k][o]
__device__ float g_swT[3 * CH * CH];

__device__ __forceinline__ float sigmoidf_(float x) { return 1.f / (1.f + expf(-x)); }

__device__ __forceinline__ void cpasync16(unsigned saddr, const void* gptr) {
    asm volatile("cp.async.cg.shared.global [%0], [%1], 16;" :: "r"(saddr), "l"(gptr));
}
__device__ __forceinline__ void cpcommit() { asm volatile("cp.async.commit_group;"); }
__device__ __forceinline__ void cpwait0()  { asm volatile("cp.async.wait_group 0;" ::: "memory"); }

// stage chunk c (8 k-rows = 256 float4 per matrix) of two weight matrices into wbuf[buf]
__device__ __forceinline__ void issue_chunk(unsigned wb0, int buf, int t,
                                            const float* fsrc, const float* gsrc, int c) {
    unsigned d = wb0 + (unsigned)buf * 8192u + (unsigned)t * 16u;
    cpasync16(d,         (const float4*)fsrc + c * 256 + t);
    cpasync16(d + 4096u, (const float4*)gsrc + c * 256 + t);
    cpcommit();
}

// scalar float4 FMA: ACC += A * B
#define FMA4(ACC, A, B) do { \
    ACC.x = fmaf((A), (B).x, ACC.x); ACC.y = fmaf((A), (B).y, ACC.y); \
    ACC.z = fmaf((A), (B).z, ACC.z); ACC.w = fmaf((A), (B).w, ACC.w); } while (0)

// ---------------- 1. stable gather per (batch, class) + zero mean buffers ----------------
__global__ void gather_kernel(const float* __restrict__ raw, const int* __restrict__ labels) {
    int seq = blockIdx.x;
    int b = seq / 10, cls = seq % 10 + 1;
    const int* lab = labels + b * SQ;
    __shared__ int cnt[256];
    __shared__ int scan[257];
    int t = threadIdx.x;
    if (t < CH0) g_mean0[seq * CH0 + t] = 0.f;
    if (t < CH)  g_mean1[seq * CH + t]  = 0.f;
    int base = t * 16;
    int c = 0;
#pragma unroll
    for (int u = 0; u < 16; u++) c += (lab[base + u] == cls);
    cnt[t] = c;
    __syncthreads();
    if (t == 0) {
        int acc = 0;
        for (int i = 0; i < 256; i++) { scan[i] = acc; acc += cnt[i]; }
        scan[256] = acc;
        g_len[seq] = acc;
    }
    __syncthreads();
    int w = scan[t];
    const float* xb = raw + (size_t)b * SQ * 3;
    float* dst = g_x + (size_t)seq * SQ * 3;
    for (int u = 0; u < 16; u++) {
        int s = base + u;
        if (lab[s] == cls) {
            dst[w * 3 + 0] = xb[s * 3 + 0];
            dst[w * 3 + 1] = xb[s * 3 + 1];
            dst[w * 3 + 2] = xb[s * 3 + 2];
            w++;
        }
    }
}

// ---------------- prep: transpose small weight matrices ----------------
__global__ void prep_kernel(const float* __restrict__ cv1_w,
                            const float* __restrict__ rw, const float* __restrict__ sw) {
    int idx = blockIdx.x * 256 + threadIdx.x;
    if (idx < CH0 * CH) {
        int k = idx / CH, o = idx % CH;
        g_cv1T[idx] = cv1_w[o * CH0 + k];
    }
    if (idx < 3 * CH * CH) {
        int st = idx / (CH * CH);
        int r = idx % (CH * CH);
        int k = r / CH, o = r % CH;
        g_rwT[idx] = rw[(size_t)st * CH * CH + o * CH + k];
        g_swT[idx] = sw[(size_t)st * CH * CH + o * CH + k];
    }
}

// ---------------- 2. cv0 (K=3) with fused SE0 mean partial-sums ----------------
__global__ void cv0_kernel(const float* __restrict__ w, const float* __restrict__ b) {
    int seq = blockIdx.y;
    int L = g_len[seq];
    int j0 = blockIdx.x * 16;
    if (j0 >= L) return;
    __shared__ float ws[CH0 * 3];
    __shared__ float bs[CH0];
    __shared__ float msum[CH0];
    int t = threadIdx.x;
    if (t < CH0 * 3) ws[t] = w[t];
    if (t < CH0) { bs[t] = b[t]; msum[t] = 0.f; }
    __syncthreads();
    int j = j0 + (t >> 4);
    int c0 = (t & 15) * 4;
    if (j < L) {
        const float* xp = g_x + ((size_t)seq * SQ + j) * 3;
        float x0 = xp[0], x1 = xp[1], x2 = xp[2];
        float* out = g_h0 + ((size_t)seq * SQ + j) * CH0;
        float v0 = fmaxf(fmaf(x0, ws[(c0+0)*3+0], fmaf(x1, ws[(c0+0)*3+1], fmaf(x2, ws[(c0+0)*3+2], bs[c0+0]))), 0.f);
        float v1 = fmaxf(fmaf(x0, ws[(c0+1)*3+0], fmaf(x1, ws[(c0+1)*3+1], fmaf(x2, ws[(c0+1)*3+2], bs[c0+1]))), 0.f);
        float v2 = fmaxf(fmaf(x0, ws[(c0+2)*3+0], fmaf(x1, ws[(c0+2)*3+1], fmaf(x2, ws[(c0+2)*3+2], bs[c0+2]))), 0.f);
        float v3 = fmaxf(fmaf(x0, ws[(c0+3)*3+0], fmaf(x1, ws[(c0+3)*3+1], fmaf(x2, ws[(c0+3)*3+2], bs[c0+3]))), 0.f);
        out[c0+0] = v0; out[c0+1] = v1; out[c0+2] = v2; out[c0+3] = v3;
        atomicAdd(&msum[c0+0], v0);
        atomicAdd(&msum[c0+1], v1);
        atomicAdd(&msum[c0+2], v2);
        atomicAdd(&msum[c0+3], v3);
    }
    __syncthreads();
    if (t < CH0) atomicAdd(&g_mean0[seq * CH0 + t], msum[t]);
}

// ---------------- SE MLP: partial sums -> mean -> sigmoid gate ----------------
// which selects g_mean0/g_mean1 in DEVICE code (host-side __device__-symbol
// args pass the host shadow address -> HMM faults -> 128MB delta -> violation).
__global__ void semlp_kernel(int which,
                             const float* __restrict__ w1, const float* __restrict__ b1,
                             const float* __restrict__ w2, const float* __restrict__ b2,
                             int ch, int H) {
    int seq = blockIdx.x;
    int t = threadIdx.x;
    __shared__ float mn[CH];
    __shared__ float hid[8];
    const float* sums = which ? g_mean1 : g_mean0;
    float inv = 1.f / fmaxf((float)g_len[seq], 1.f);
    mn[t] = sums[seq * ch + t] * inv;
    __syncthreads();
    if (t < H) {
        float a = b1[t];
        for (int k = 0; k < ch; k++) a = fmaf(mn[k], w1[t * ch + k], a);
        hid[t] = fmaxf(a, 0.f);
    }
    __syncthreads();
    float a = b2[t];
    for (int hh = 0; hh < H; hh++) a = fmaf(hid[hh], w2[t * H + hh], a);
    g_e[seq * CH + t] = sigmoidf_(a);
}

// ---------------- 3. cv1 GEMM (SE0 folded into weights) + fused SE1 mean sums ----------------
__global__ void cv1_kernel(const float* __restrict__ cb) {
    int seq = blockIdx.y;
    int L = g_len[seq];
    int j0 = blockIdx.x * 32;
    if (j0 >= L) return;
    __shared__ __align__(16) float hs[32 * CH0];
    __shared__ __align__(16) float ws[CH0 * CH];
    __shared__ float sred[8 * CH];
    const float* eb = g_e + seq * CH;
    for (int idx = threadIdx.x; idx < CH0 * CH; idx += 256)
        ws[idx] = g_cv1T[idx] * eb[idx >> 7];   // fold SE0 gate
    const float* hp = g_h0 + (size_t)seq * SQ * CH0;
    for (int idx = threadIdx.x; idx < 32 * CH0; idx += 256) {
        int r = idx >> 6;
        int j = j0 + r;
        hs[idx] = (j < L) ? hp[(size_t)j * CH0 + (idx & 63)] : 0.f;
    }
    __syncthreads();
    int ty = threadIdx.x >> 5, tx = threadIdx.x & 31;
    float acc[16];
#pragma unroll
    for (int i = 0; i < 16; i++) acc[i] = 0.f;
#pragma unroll 4
    for (int k = 0; k < CH0; k++) {
        float a0 = hs[(ty * 4 + 0) * CH0 + k];
        float a1 = hs[(ty * 4 + 1) * CH0 + k];
        float a2 = hs[(ty * 4 + 2) * CH0 + k];
        float a3 = hs[(ty * 4 + 3) * CH0 + k];
        float4 bv = *(const float4*)&ws[k * CH + tx * 4];
        acc[0]  = fmaf(a0, bv.x, acc[0]);  acc[1]  = fmaf(a0, bv.y, acc[1]);
        acc[2]  = fmaf(a0, bv.z, acc[2]);  acc[3]  = fmaf(a0, bv.w, acc[3]);
        acc[4]  = fmaf(a1, bv.x, acc[4]);  acc[5]  = fmaf(a1, bv.y, acc[5]);
        acc[6]  = fmaf(a1, bv.z, acc[6]);  acc[7]  = fmaf(a1, bv.w, acc[7]);
        acc[8]  = fmaf(a2, bv.x, acc[8]);  acc[9]  = fmaf(a2, bv.y, acc[9]);
        acc[10] = fmaf(a2, bv.z, acc[10]); acc[11] = fmaf(a2, bv.w, acc[11]);
        acc[12] = fmaf(a3, bv.x, acc[12]); acc[13] = fmaf(a3, bv.y, acc[13]);
        acc[14] = fmaf(a3, bv.z, acc[14]); acc[15] = fmaf(a3, bv.w, acc[15]);
    }
    float* out = g_bufA + (size_t)seq * SQ * CH;
    float cs0 = 0.f, cs1 = 0.f, cs2 = 0.f, cs3 = 0.f;
#pragma unroll
    for (int p = 0; p < 4; p++) {
        int j = j0 + ty * 4 + p;
        if (j < L) {
            int c = tx * 4;
            float v0 = fmaxf(acc[p * 4 + 0] + cb[c + 0], 0.f);
            float v1 = fmaxf(acc[p * 4 + 1] + cb[c + 1], 0.f);
            float v2 = fmaxf(acc[p * 4 + 2] + cb[c + 2], 0.f);
            float v3 = fmaxf(acc[p * 4 + 3] + cb[c + 3], 0.f);
            out[(size_t)j * CH + c + 0] = v0;
            out[(size_t)j * CH + c + 1] = v1;
            out[(size_t)j * CH + c + 2] = v2;
            out[(size_t)j * CH + c + 3] = v3;
            cs0 += v0; cs1 += v1; cs2 += v2; cs3 += v3;
        }
    }
    sred[ty * CH + tx * 4 + 0] = cs0;
    sred[ty * CH + tx * 4 + 1] = cs1;
    sred[ty * CH + tx * 4 + 2] = cs2;
    sred[ty * CH + tx * 4 + 3] = cs3;
    __syncthreads();
    if (threadIdx.x < CH) {
        float s = 0.f;
#pragma unroll
        for (int w = 0; w < 8; w++) s += sred[w * CH + threadIdx.x];
        atomicAdd(&g_mean1[seq * CH + threadIdx.x], s);
    }
}

// ---------------- 4. residual block: cp.async double-buffered weight staging ----------------
// 32-row tiles, 256 threads, chunk = 8 k-rows.
// Pipeline per chunk: wait_group 0 -> sync -> issue(c+1) -> compute(c).
__global__ void resblock_kernel(int flip,
                                const float* __restrict__ fw, const float* __restrict__ fb,
                                const float* __restrict__ gw, const float* __restrict__ gb,
                                const float* __restrict__ rb, const float* __restrict__ sb,
                                int stack, int skip_init, int applyE, int last) {
    int seq = blockIdx.y;
    int L = g_len[seq];
    int j0 = blockIdx.x * 32;
    if (j0 >= L) return;
    const float* hin = flip ? g_bufB : g_bufA;
    float* hout      = flip ? g_bufA : g_bufB;
    const float* rwT = g_rwT + (size_t)stack * CH * CH;
    const float* swT = g_swT + (size_t)stack * CH * CH;

    __shared__ __align__(16) float hs[34 * CH];          // rows j0-1 .. j0+32
    __shared__ __align__(16) float wbuf[2][2][8 * CH];   // [buf][f/g][k2*128+col]
    __shared__ float es[CH];

    int t = threadIdx.x;
    int ty = t >> 5, tx = t & 31;
    int ty4 = ty * 4;

    if (t < CH) es[t] = applyE ? g_e[seq * CH + t] : 1.f;
    __syncthreads();

    const float* hp = hin + (size_t)seq * SQ * CH;
    {
        const float4* e4 = (const float4*)es;
        float4* hs4 = (float4*)hs;
        for (int idx = t; idx < 34 * 32; idx += 256) {
            int r = idx >> 5;
            int c4 = idx & 31;
            int j = j0 - 1 + r;
            float4 v = make_float4(0.f, 0.f, 0.f, 0.f);
            if (j >= 0 && j < L) {
                v = ((const float4*)(hp + (size_t)j * CH))[c4];
                float4 e = e4[c4];
                v.x *= e.x; v.y *= e.y; v.z *= e.z; v.w *= e.w;
            }
            hs4[idx] = v;
        }
    }

    unsigned wb0 = (unsigned)__cvta_generic_to_shared(&wbuf[0][0][0]);

    float4 F0 = make_float4(0.f,0.f,0.f,0.f), F1 = F0, F2 = F0, F3 = F0;
    float4 G0 = F0, G1 = F0, G2 = F0, G3 = F0;

    // ---- phase 1: f/g conv GEMM, K=384 -> 48 chunks of 8 ----
    issue_chunk(wb0, 0, t, fw, gw, 0);
#pragma unroll 1
    for (int c = 0; c < 48; c++) {
        cpwait0();
        __syncthreads();
        if (c < 47) issue_chunk(wb0, (c + 1) & 1, t, fw, gw, c + 1);
        const float4* wf4 = (const float4*)&wbuf[c & 1][0][0];
        const float4* wg4 = (const float4*)&wbuf[c & 1][1][0];
#pragma unroll
        for (int k2 = 0; k2 < 8; k2++) {
            int kk = c * 8 + k2;
            float a0 = hs[(ty4 + 0) * CH + kk];
            float a1 = hs[(ty4 + 1) * CH + kk];
            float a2 = hs[(ty4 + 2) * CH + kk];
            float a3 = hs[(ty4 + 3) * CH + kk];
            float4 bf = wf4[k2 * 32 + tx];
            float4 bg = wg4[k2 * 32 + tx];
            FMA4(F0, a0, bf); FMA4(F1, a1, bf); FMA4(F2, a2, bf); FMA4(F3, a3, bf);
            FMA4(G0, a0, bg); FMA4(G1, a1, bg); FMA4(G2, a2, bg); FMA4(G3, a3, bg);
        }
    }
    __syncthreads();   // all hs reads complete

    // ---- gated nonlinearity -> zg tile (rows 0..31 of hs) + prefetch phase-2 chunk 0 ----
    issue_chunk(wb0, 0, t, rwT, swT, 0);
    {
        float4 fbv = ((const float4*)fb)[tx];
        float4 gbv = ((const float4*)gb)[tx];
        float4 z;
        z.x = tanhf(F0.x + fbv.x) * sigmoidf_(G0.x + gbv.x);
        z.y = tanhf(F0.y + fbv.y) * sigmoidf_(G0.y + gbv.y);
        z.z = tanhf(F0.z + fbv.z) * sigmoidf_(G0.z + gbv.z);
        z.w = tanhf(F0.w + fbv.w) * sigmoidf_(G0.w + gbv.w);
        ((float4*)&hs[(ty4 + 0) * CH])[tx] = z;
        z.x = tanhf(F1.x + fbv.x) * sigmoidf_(G1.x + gbv.x);
        z.y = tanhf(F1.y + fbv.y) * sigmoidf_(G1.y + gbv.y);
        z.z = tanhf(F1.z + fbv.z) * sigmoidf_(G1.z + gbv.z);
        z.w = tanhf(F1.w + fbv.w) * sigmoidf_(G1.w + gbv.w);
        ((float4*)&hs[(ty4 + 1) * CH])[tx] = z;
        z.x = tanhf(F2.x + fbv.x) * sigmoidf_(G2.x + gbv.x);
        z.y = tanhf(F2.y + fbv.y) * sigmoidf_(G2.y + gbv.y);
        z.z = tanhf(F2.z + fbv.z) * sigmoidf_(G2.z + gbv.z);
        z.w = tanhf(F2.w + fbv.w) * sigmoidf_(G2.w + gbv.w);
        ((float4*)&hs[(ty4 + 2) * CH])[tx] = z;
        z.x = tanhf(F3.x + fbv.x) * sigmoidf_(G3.x + gbv.x);
        z.y = tanhf(F3.y + fbv.y) * sigmoidf_(G3.y + gbv.y);
        z.z = tanhf(F3.z + fbv.z) * sigmoidf_(G3.z + gbv.z);
        z.w = tanhf(F3.w + fbv.w) * sigmoidf_(G3.w + gbv.w);
        ((float4*)&hs[(ty4 + 3) * CH])[tx] = z;
    }
    F0 = make_float4(0.f,0.f,0.f,0.f); F1 = F0; F2 = F0; F3 = F0;
    G0 = F0; G1 = F0; G2 = F0; G3 = F0;

    // ---- phase 2: res/skip GEMM, K=128 -> 16 chunks of 8 ----
#pragma unroll 1
    for (int c = 0; c < 16; c++) {
        cpwait0();
        __syncthreads();   // (c==0: also orders zg writes before reads)
        if (c < 15) issue_chunk(wb0, (c + 1) & 1, t, rwT, swT, c + 1);
        const float4* wf4 = (const float4*)&wbuf[c & 1][0][0];
        const float4* wg4 = (const float4*)&wbuf[c & 1][1][0];
#pragma unroll
        for (int k2 = 0; k2 < 8; k2++) {
            int kk = c * 8 + k2;
            float a0 = hs[(ty4 + 0) * CH + kk];
            float a1 = hs[(ty4 + 1) * CH + kk];
            float a2 = hs[(ty4 + 2) * CH + kk];
            float a3 = hs[(ty4 + 3) * CH + kk];
            float4 br = wf4[k2 * 32 + tx];
            float4 bs = wg4[k2 * 32 + tx];
            FMA4(F0, a0, br); FMA4(F1, a1, br); FMA4(F2, a2, br); FMA4(F3, a3, br);
            FMA4(G0, a0, bs); FMA4(G1, a1, bs); FMA4(G2, a2, bs); FMA4(G3, a3, bs);
        }
    }

    // ---- epilogue ----
    float* outr = hout + (size_t)seq * SQ * CH;
    float* outs = g_skip + (size_t)seq * SQ * CH;
    float4 rbv = ((const float4*)rb)[tx];
    float4 sbv = ((const float4*)sb)[tx];
    float4 ev  = ((const float4*)es)[tx];

#define EPILOG(ROW, FACC, GACC)                                                  \
    do {                                                                         \
        int j = j0 + ty4 + (ROW);                                                \
        if (j < L) {                                                             \
            float4 hv = ((const float4*)(hp + (size_t)j * CH))[tx];              \
            float4 o;                                                            \
            o.x = FACC.x + rbv.x + hv.x * ev.x;                                  \
            o.y = FACC.y + rbv.y + hv.y * ev.y;                                  \
            o.z = FACC.z + rbv.z + hv.z * ev.z;                                  \
            o.w = FACC.w + rbv.w + hv.w * ev.w;                                  \
            float4 s;                                                            \
            s.x = GACC.x + sbv.x; s.y = GACC.y + sbv.y;                          \
            s.z = GACC.z + sbv.z; s.w = GACC.w + sbv.w;                          \
            if (!skip_init) {                                                    \
                float4 old = ((const float4*)(outs + (size_t)j * CH))[tx];       \
                s.x += old.x; s.y += old.y; s.z += old.z; s.w += old.w;          \
            }                                                                    \
            if (last) {                                                          \
                s.x += o.x; s.y += o.y; s.z += o.z; s.w += o.w;                  \
                ((float4*)(outs + (size_t)j * CH))[tx] = s;                      \
            } else {                                                             \
                ((float4*)(outr + (size_t)j * CH))[tx] = o;                      \
                ((float4*)(outs + (size_t)j * CH))[tx] = s;                      \
            }                                                                    \
        }                                                                        \
    } while (0)

    EPILOG(0, F0, G0);
    EPILOG(1, F1, G1);
    EPILOG(2, F2, G2);
    EPILOG(3, F3, G3);
#undef EPILOG
}

// ---------------- 5. masked avg/max pool (reads fused res+skip from g_skip) ----------------
__global__ void finalize_kernel() {
    int seq = blockIdx.x;
    int L = g_len[seq];
    int t = threadIdx.x;
    int c = t & 127, half = t >> 7;
    const float* s = g_skip + (size_t)seq * SQ * CH + c;
    float sum = 0.f, mx = -INFINITY;
    for (int j = half; j < L; j += 2) {
        float v = s[(size_t)j * CH];
        sum += v;
        mx = fmaxf(mx, v);
    }
    __shared__ float ssum[256], smx[256];
    ssum[t] = sum; smx[t] = mx;
    __syncthreads();
    if (t < 128) {
        float su = ssum[t] + ssum[t + 128];
        float m = fmaxf(smx[t], smx[t + 128]);
        if (L == 0) m = 0.f;
        float cnt = fmaxf((float)L, 1.f);
        g_feat[seq * 2 * CH + 2 * t]     = su / cnt;
        g_feat[seq * 2 * CH + 2 * t + 1] = m;
    }
}

// ---------------- 6. head MLP ----------------
__global__ void head_kernel(const float* __restrict__ l1w, const float* __restrict__ l1b,
                            const float* __restrict__ l2w, const float* __restrict__ l2b,
                            float* __restrict__ out) {
    int seq = blockIdx.x, t = threadIdx.x;
    __shared__ float fs[256];
    __shared__ float r0[256], r1[256];
    fs[t] = g_feat[seq * 256 + t];
    __syncthreads();
    float o0 = 0.f, o1 = 0.f;
    for (int u = t; u < 1024; u += 256) {
        const float* w = l1w + (size_t)u * 256;
        float a = l1b[u];
#pragma unroll 8
        for (int v = 0; v < 256; v++) a = fmaf(fs[v], w[v], a);
        float hv = fmaxf(a, 0.f);
        o0 = fmaf(hv, l2w[u], o0);
        o1 = fmaf(hv, l2w[1024 + u], o1);
    }
    r0[t] = o0; r1[t] = o1;
    __syncthreads();
    for (int st = 128; st > 0; st >>= 1) {
        if (t < st) { r0[t] += r0[t + st]; r1[t] += r1[t + st]; }
        __syncthreads();
    }
    if (t == 0) {
        out[seq * 2 + 0] = r0[0] + l2b[0];
        out[seq * 2 + 1] = r1[0] + l2b[1];
    }
}

// ---------------- launch ----------------
extern "C" void kernel_launch(void* const* d_in, const int* in_sizes, int n_in,
                              void* d_out, int out_size) {
    const float* raw    = (const float*)d_in[0];
    const int*   labels = (const int*)  d_in[1];
    const float* cv0_w  = (const float*)d_in[2];
    const float* cv0_b  = (const float*)d_in[3];
    const float* se0_w1 = (const float*)d_in[4];
    const float* se0_b1 = (const float*)d_in[5];
    const float* se0_w2 = (const float*)d_in[6];
    const float* se0_b2 = (const float*)d_in[7];
    const float* cv1_w  = (const float*)d_in[8];
    const float* cv1_b  = (const float*)d_in[9];
    const float* se1_w1 = (const float*)d_in[10];
    const float* se1_b1 = (const float*)d_in[11];
    const float* se1_w2 = (const float*)d_in[12];
    const float* se1_b2 = (const float*)d_in[13];
    const float* rs_fw  = (const float*)d_in[14];
    const float* rs_fb  = (const float*)d_in[15];
    const float* rs_gw  = (const float*)d_in[16];
    const float* rs_gb  = (const float*)d_in[17];
    const float* rs_rw  = (const float*)d_in[18];
    const float* rs_rb  = (const float*)d_in[19];
    const float* rs_sw  = (const float*)d_in[20];
    const float* rs_sb  = (const float*)d_in[21];
    const float* l1_w   = (const float*)d_in[22];
    const float* l1_b   = (const float*)d_in[23];
    const float* l2_w   = (const float*)d_in[24];
    const float* l2_b   = (const float*)d_in[25];
    float* out = (float*)d_out;

    gather_kernel<<<NSEQ, 256>>>(raw, labels);
    prep_kernel<<<192, 256>>>(cv1_w, rs_rw, rs_sw);
    cv0_kernel<<<dim3(256, NSEQ), 256>>>(cv0_w, cv0_b);
    semlp_kernel<<<NSEQ, 64>>>(0, se0_w1, se0_b1, se0_w2, se0_b2, 64, 4);
    cv1_kernel<<<dim3(128, NSEQ), 256>>>(cv1_b);
    semlp_kernel<<<NSEQ, 128>>>(1, se1_w1, se1_b1, se1_w2, se1_b2, 128, 8);

    for (int st = 0; st < 3; st++) {
        int flip = st & 1;  // 0: A->B, 1: B->A, 2: A->(fused into g_skip)
        resblock_kernel<<<dim3(128, NSEQ), 256>>>(
            flip,
            rs_fw + (size_t)st * 3 * CH * CH, rs_fb + st * CH,
            rs_gw + (size_t)st * 3 * CH * CH, rs_gb + st * CH,
            rs_rb + st * CH, rs_sb + st * CH,
            st, st == 0, st == 0, st == 2);
    }
    finalize_kernel<<<NSEQ, 256>>>();
    head_kernel<<<NSEQ, 256>>>(l1_w, l1_b, l2_w, l2_b, out);
}

// round 10
// speedup vs baseline: 1.3251x; 1.0394x over previous
#include <cuda_runtime.h>
#include <cstdint>
#include <math.h>

#define SQ   4096
#define NSEQ 80
#define CH   128
#define CH0  64

// ---------------- device scratch ----------------
__device__ int   g_len[NSEQ];
__device__ float g_x[NSEQ * SQ * 3];
__device__ float g_h0[(size_t)NSEQ * SQ * CH0];
__device__ float g_bufA[(size_t)NSEQ * SQ * CH];
__device__ float g_bufB[(size_t)NSEQ * SQ * CH];
__device__ float g_skip[(size_t)NSEQ * SQ * CH];
__device__ float g_mean0[NSEQ * CH0];
__device__ float g_mean1[NSEQ * CH];
__device__ float g_e[NSEQ * CH];
__device__ float g_feat[NSEQ * 2 * CH];
__device__ float g_cv1T[CH0 * CH];       // cv1_w transposed [k][o]
__device__ float g_rwT[3 * CH * CH];     // rs_rw transposed per stack [k][o]
__device__ float g_swT[3 * CH * CH];

__device__ __forceinline__ float sigmoidf_(float x) { return 1.f / (1.f + expf(-x)); }

__device__ __forceinline__ void cpasync16(unsigned saddr, const void* gptr) {
    asm volatile("cp.async.cg.shared.global [%0], [%1], 16;" :: "r"(saddr), "l"(gptr));
}
__device__ __forceinline__ void cpcommit() { asm volatile("cp.async.commit_group;"); }
__device__ __forceinline__ void cpwait0()  { asm volatile("cp.async.wait_group 0;" ::: "memory"); }

// stage chunk c (8 k-rows = 256 float4 per matrix) of two weight matrices into wbuf[buf]
__device__ __forceinline__ void issue_chunk(unsigned wb0, int buf, int t,
                                            const float* fsrc, const float* gsrc, int c) {
    unsigned d = wb0 + (unsigned)buf * 8192u + (unsigned)t * 16u;
    cpasync16(d,         (const float4*)fsrc + c * 256 + t);
    cpasync16(d + 4096u, (const float4*)gsrc + c * 256 + t);
    cpcommit();
}

// ---- packed f32x2 helpers (Blackwell) ----
#define PK2(D, LO, HI) \
    asm("mov.b64 %0, {%1, %2};" : "=l"(D) : "f"(LO), "f"(HI))
#define UPK2(LO, HI, S) \
    asm("mov.b64 {%0, %1}, %2;" : "=f"(LO), "=f"(HI) : "l"(S))
#define FMA2(ACC, A, W) \
    asm("fma.rn.f32x2 %0, %1, %2, %0;" : "+l"(ACC) : "l"(A), "l"(W))

// ---------------- 1. stable gather per (batch, class) + zero mean buffers ----------------
__global__ void gather_kernel(const float* __restrict__ raw, const int* __restrict__ labels) {
    int seq = blockIdx.x;
    int b = seq / 10, cls = seq % 10 + 1;
    const int* lab = labels + b * SQ;
    __shared__ int cnt[256];
    __shared__ int scan[257];
    int t = threadIdx.x;
    if (t < CH0) g_mean0[seq * CH0 + t] = 0.f;
    if (t < CH)  g_mean1[seq * CH + t]  = 0.f;
    int base = t * 16;
    int c = 0;
#pragma unroll
    for (int u = 0; u < 16; u++) c += (lab[base + u] == cls);
    cnt[t] = c;
    __syncthreads();
    if (t == 0) {
        int acc = 0;
        for (int i = 0; i < 256; i++) { scan[i] = acc; acc += cnt[i]; }
        scan[256] = acc;
        g_len[seq] = acc;
    }
    __syncthreads();
    int w = scan[t];
    const float* xb = raw + (size_t)b * SQ * 3;
    float* dst = g_x + (size_t)seq * SQ * 3;
    for (int u = 0; u < 16; u++) {
        int s = base + u;
        if (lab[s] == cls) {
            dst[w * 3 + 0] = xb[s * 3 + 0];
            dst[w * 3 + 1] = xb[s * 3 + 1];
            dst[w * 3 + 2] = xb[s * 3 + 2];
            w++;
        }
    }
}

// ---------------- prep: transpose small weight matrices ----------------
__global__ void prep_kernel(const float* __restrict__ cv1_w,
                            const float* __restrict__ rw, const float* __restrict__ sw) {
    int idx = blockIdx.x * 256 + threadIdx.x;
    if (idx < CH0 * CH) {
        int k = idx / CH, o = idx % CH;
        g_cv1T[idx] = cv1_w[o * CH0 + k];
    }
    if (idx < 3 * CH * CH) {
        int st = idx / (CH * CH);
        int r = idx % (CH * CH);
        int k = r / CH, o = r % CH;
        g_rwT[idx] = rw[(size_t)st * CH * CH + o * CH + k];
        g_swT[idx] = sw[(size_t)st * CH * CH + o * CH + k];
    }
}

// ---------------- 2. cv0 (K=3) with fused SE0 mean partial-sums ----------------
__global__ void cv0_kernel(const float* __restrict__ w, const float* __restrict__ b) {
    int seq = blockIdx.y;
    int L = g_len[seq];
    int j0 = blockIdx.x * 16;
    if (j0 >= L) return;
    __shared__ float ws[CH0 * 3];
    __shared__ float bs[CH0];
    __shared__ float msum[CH0];
    int t = threadIdx.x;
    if (t < CH0 * 3) ws[t] = w[t];
    if (t < CH0) { bs[t] = b[t]; msum[t] = 0.f; }
    __syncthreads();
    int j = j0 + (t >> 4);
    int c0 = (t & 15) * 4;
    if (j < L) {
        const float* xp = g_x + ((size_t)seq * SQ + j) * 3;
        float x0 = xp[0], x1 = xp[1], x2 = xp[2];
        float* out = g_h0 + ((size_t)seq * SQ + j) * CH0;
        float v0 = fmaxf(fmaf(x0, ws[(c0+0)*3+0], fmaf(x1, ws[(c0+0)*3+1], fmaf(x2, ws[(c0+0)*3+2], bs[c0+0]))), 0.f);
        float v1 = fmaxf(fmaf(x0, ws[(c0+1)*3+0], fmaf(x1, ws[(c0+1)*3+1], fmaf(x2, ws[(c0+1)*3+2], bs[c0+1]))), 0.f);
        float v2 = fmaxf(fmaf(x0, ws[(c0+2)*3+0], fmaf(x1, ws[(c0+2)*3+1], fmaf(x2, ws[(c0+2)*3+2], bs[c0+2]))), 0.f);
        float v3 = fmaxf(fmaf(x0, ws[(c0+3)*3+0], fmaf(x1, ws[(c0+3)*3+1], fmaf(x2, ws[(c0+3)*3+2], bs[c0+3]))), 0.f);
        out[c0+0] = v0; out[c0+1] = v1; out[c0+2] = v2; out[c0+3] = v3;
        atomicAdd(&msum[c0+0], v0);
        atomicAdd(&msum[c0+1], v1);
        atomicAdd(&msum[c0+2], v2);
        atomicAdd(&msum[c0+3], v3);
    }
    __syncthreads();
    if (t < CH0) atomicAdd(&g_mean0[seq * CH0 + t], msum[t]);
}

// ---------------- SE MLP: partial sums -> mean -> sigmoid gate ----------------
// which selects g_mean0/g_mean1 in DEVICE code (host-side __device__-symbol
// args pass the host shadow address -> HMM faults -> 128MB delta -> violation).
__global__ void semlp_kernel(int which,
                             const float* __restrict__ w1, const float* __restrict__ b1,
                             const float* __restrict__ w2, const float* __restrict__ b2,
                             int ch, int H) {
    int seq = blockIdx.x;
    int t = threadIdx.x;
    __shared__ float mn[CH];
    __shared__ float hid[8];
    const float* sums = which ? g_mean1 : g_mean0;
    float inv = 1.f / fmaxf((float)g_len[seq], 1.f);
    mn[t] = sums[seq * ch + t] * inv;
    __syncthreads();
    if (t < H) {
        float a = b1[t];
        for (int k = 0; k < ch; k++) a = fmaf(mn[k], w1[t * ch + k], a);
        hid[t] = fmaxf(a, 0.f);
    }
    __syncthreads();
    float a = b2[t];
    for (int hh = 0; hh < H; hh++) a = fmaf(hid[hh], w2[t * H + hh], a);
    g_e[seq * CH + t] = sigmoidf_(a);
}

// ---------------- 3. cv1 GEMM (SE0 folded into weights) + fused SE1 mean sums ----------------
__global__ void cv1_kernel(const float* __restrict__ cb) {
    int seq = blockIdx.y;
    int L = g_len[seq];
    int j0 = blockIdx.x * 32;
    if (j0 >= L) return;
    __shared__ __align__(16) float hs[32 * CH0];
    __shared__ __align__(16) float ws[CH0 * CH];
    __shared__ float sred[8 * CH];
    const float* eb = g_e + seq * CH;
    for (int idx = threadIdx.x; idx < CH0 * CH; idx += 256)
        ws[idx] = g_cv1T[idx] * eb[idx >> 7];   // fold SE0 gate
    const float* hp = g_h0 + (size_t)seq * SQ * CH0;
    for (int idx = threadIdx.x; idx < 32 * CH0; idx += 256) {
        int r = idx >> 6;
        int j = j0 + r;
        hs[idx] = (j < L) ? hp[(size_t)j * CH0 + (idx & 63)] : 0.f;
    }
    __syncthreads();
    int ty = threadIdx.x >> 5, tx = threadIdx.x & 31;
    float acc[16];
#pragma unroll
    for (int i = 0; i < 16; i++) acc[i] = 0.f;
#pragma unroll 4
    for (int k = 0; k < CH0; k++) {
        float a0 = hs[(ty * 4 + 0) * CH0 + k];
        float a1 = hs[(ty * 4 + 1) * CH0 + k];
        float a2 = hs[(ty * 4 + 2) * CH0 + k];
        float a3 = hs[(ty * 4 + 3) * CH0 + k];
        float4 bv = *(const float4*)&ws[k * CH + tx * 4];
        acc[0]  = fmaf(a0, bv.x, acc[0]);  acc[1]  = fmaf(a0, bv.y, acc[1]);
        acc[2]  = fmaf(a0, bv.z, acc[2]);  acc[3]  = fmaf(a0, bv.w, acc[3]);
        acc[4]  = fmaf(a1, bv.x, acc[4]);  acc[5]  = fmaf(a1, bv.y, acc[5]);
        acc[6]  = fmaf(a1, bv.z, acc[6]);  acc[7]  = fmaf(a1, bv.w, acc[7]);
        acc[8]  = fmaf(a2, bv.x, acc[8]);  acc[9]  = fmaf(a2, bv.y, acc[9]);
        acc[10] = fmaf(a2, bv.z, acc[10]); acc[11] = fmaf(a2, bv.w, acc[11]);
        acc[12] = fmaf(a3, bv.x, acc[12]); acc[13] = fmaf(a3, bv.y, acc[13]);
        acc[14] = fmaf(a3, bv.z, acc[14]); acc[15] = fmaf(a3, bv.w, acc[15]);
    }
    float* out = g_bufA + (size_t)seq * SQ * CH;
    float cs0 = 0.f, cs1 = 0.f, cs2 = 0.f, cs3 = 0.f;
#pragma unroll
    for (int p = 0; p < 4; p++) {
        int j = j0 + ty * 4 + p;
        if (j < L) {
            int c = tx * 4;
            float v0 = fmaxf(acc[p * 4 + 0] + cb[c + 0], 0.f);
            float v1 = fmaxf(acc[p * 4 + 1] + cb[c + 1], 0.f);
            float v2 = fmaxf(acc[p * 4 + 2] + cb[c + 2], 0.f);
            float v3 = fmaxf(acc[p * 4 + 3] + cb[c + 3], 0.f);
            out[(size_t)j * CH + c + 0] = v0;
            out[(size_t)j * CH + c + 1] = v1;
            out[(size_t)j * CH + c + 2] = v2;
            out[(size_t)j * CH + c + 3] = v3;
            cs0 += v0; cs1 += v1; cs2 += v2; cs3 += v3;
        }
    }
    sred[ty * CH + tx * 4 + 0] = cs0;
    sred[ty * CH + tx * 4 + 1] = cs1;
    sred[ty * CH + tx * 4 + 2] = cs2;
    sred[ty * CH + tx * 4 + 3] = cs3;
    __syncthreads();
    if (threadIdx.x < CH) {
        float s = 0.f;
#pragma unroll
        for (int w = 0; w < 8; w++) s += sred[w * CH + threadIdx.x];
        atomicAdd(&g_mean1[seq * CH + threadIdx.x], s);
    }
}

// ---------------- 4. residual block: cp.async double buffer + packed fma.rn.f32x2 ----------
// 32-row tiles, 256 threads, chunk = 8 k-rows.
// Accumulators: 16 named u64 (f32x2 pairs): F{r}{A,B} = f cols (0,1)/(2,3), G likewise.
__global__ void resblock_kernel(int flip,
                                const float* __restrict__ fw, const float* __restrict__ fb,
                                const float* __restrict__ gw, const float* __restrict__ gb,
                                const float* __restrict__ rb, const float* __restrict__ sb,
                                int stack, int skip_init, int applyE, int last) {
    int seq = blockIdx.y;
    int L = g_len[seq];
    int j0 = blockIdx.x * 32;
    if (j0 >= L) return;
    const float* hin = flip ? g_bufB : g_bufA;
    float* hout      = flip ? g_bufA : g_bufB;
    const float* rwT = g_rwT + (size_t)stack * CH * CH;
    const float* swT = g_swT + (size_t)stack * CH * CH;

    __shared__ __align__(16) float hs[34 * CH];          // rows j0-1 .. j0+32
    __shared__ __align__(16) float wbuf[2][2][8 * CH];   // [buf][f/g][k2*128+col]
    __shared__ float es[CH];

    int t = threadIdx.x;
    int ty = t >> 5, tx = t & 31;
    int ty4 = ty * 4;

    if (t < CH) es[t] = applyE ? g_e[seq * CH + t] : 1.f;
    __syncthreads();

    const float* hp = hin + (size_t)seq * SQ * CH;
    {
        const float4* e4 = (const float4*)es;
        float4* hs4 = (float4*)hs;
        for (int idx = t; idx < 34 * 32; idx += 256) {
            int r = idx >> 5;
            int c4 = idx & 31;
            int j = j0 - 1 + r;
            float4 v = make_float4(0.f, 0.f, 0.f, 0.f);
            if (j >= 0 && j < L) {
                v = ((const float4*)(hp + (size_t)j * CH))[c4];
                float4 e = e4[c4];
                v.x *= e.x; v.y *= e.y; v.z *= e.z; v.w *= e.w;
            }
            hs4[idx] = v;
        }
    }

    unsigned wb0 = (unsigned)__cvta_generic_to_shared(&wbuf[0][0][0]);

    unsigned long long F0A = 0, F0B = 0, F1A = 0, F1B = 0;
    unsigned long long F2A = 0, F2B = 0, F3A = 0, F3B = 0;
    unsigned long long G0A = 0, G0B = 0, G1A = 0, G1B = 0;
    unsigned long long G2A = 0, G2B = 0, G3A = 0, G3B = 0;

#define STEP(R, AVAL) do {                                                     \
        unsigned long long _ap;                                                \
        PK2(_ap, (AVAL), (AVAL));                                              \
        FMA2(F##R##A, _ap, bfA); FMA2(F##R##B, _ap, bfB);                      \
        FMA2(G##R##A, _ap, bgA); FMA2(G##R##B, _ap, bgB);                      \
    } while (0)

    // ---- phase 1: f/g conv GEMM, K=384 -> 48 chunks of 8 ----
    issue_chunk(wb0, 0, t, fw, gw, 0);
#pragma unroll 1
    for (int c = 0; c < 48; c++) {
        cpwait0();
        __syncthreads();
        if (c < 47) issue_chunk(wb0, (c + 1) & 1, t, fw, gw, c + 1);
        const float* wf = &wbuf[c & 1][0][0];
        const float* wg = &wbuf[c & 1][1][0];
#pragma unroll
        for (int k2 = 0; k2 < 8; k2++) {
            int kk = c * 8 + k2;
            float a0 = hs[(ty4 + 0) * CH + kk];
            float a1 = hs[(ty4 + 1) * CH + kk];
            float a2 = hs[(ty4 + 2) * CH + kk];
            float a3 = hs[(ty4 + 3) * CH + kk];
            ulonglong2 bfp = *(const ulonglong2*)(wf + k2 * CH + tx * 4);
            ulonglong2 bgp = *(const ulonglong2*)(wg + k2 * CH + tx * 4);
            unsigned long long bfA = bfp.x, bfB = bfp.y;
            unsigned long long bgA = bgp.x, bgB = bgp.y;
            STEP(0, a0); STEP(1, a1); STEP(2, a2); STEP(3, a3);
        }
    }
    __syncthreads();   // all hs reads complete

    // ---- gated nonlinearity -> zg tile (rows 0..31 of hs) + prefetch phase-2 chunk 0 ----
    issue_chunk(wb0, 0, t, rwT, swT, 0);
    {
        float4 fbv = ((const float4*)fb)[tx];
        float4 gbv = ((const float4*)gb)[tx];
#define GATE(R, ROW) do {                                                      \
            float fx, fy, fz, fw_, gx, gy, gz, gw_;                            \
            UPK2(fx, fy, F##R##A); UPK2(fz, fw_, F##R##B);                     \
            UPK2(gx, gy, G##R##A); UPK2(gz, gw_, G##R##B);                     \
            float4 z;                                                          \
            z.x = tanhf(fx + fbv.x) * sigmoidf_(gx + gbv.x);                   \
            z.y = tanhf(fy + fbv.y) * sigmoidf_(gy + gbv.y);                   \
            z.z = tanhf(fz + fbv.z) * sigmoidf_(gz + gbv.z);                   \
            z.w = tanhf(fw_ + fbv.w) * sigmoidf_(gw_ + gbv.w);                 \
            ((float4*)&hs[(ty4 + (ROW)) * CH])[tx] = z;                        \
        } while (0)
        GATE(0, 0); GATE(1, 1); GATE(2, 2); GATE(3, 3);
#undef GATE
    }
    F0A = F0B = F1A = F1B = F2A = F2B = F3A = F3B = 0ull;
    G0A = G0B = G1A = G1B = G2A = G2B = G3A = G3B = 0ull;

    // ---- phase 2: res/skip GEMM, K=128 -> 16 chunks of 8 ----
#pragma unroll 1
    for (int c = 0; c < 16; c++) {
        cpwait0();
        __syncthreads();   // (c==0: also orders zg writes before reads)
        if (c < 15) issue_chunk(wb0, (c + 1) & 1, t, rwT, swT, c + 1);
        const float* wf = &wbuf[c & 1][0][0];
        const float* wg = &wbuf[c & 1][1][0];
#pragma unroll
        for (int k2 = 0; k2 < 8; k2++) {
            int kk = c * 8 + k2;
            float a0 = hs[(ty4 + 0) * CH + kk];
            float a1 = hs[(ty4 + 1) * CH + kk];
            float a2 = hs[(ty4 + 2) * CH + kk];
            float a3 = hs[(ty4 + 3) * CH + kk];
            ulonglong2 bfp = *(const ulonglong2*)(wf + k2 * CH + tx * 4);
            ulonglong2 bgp = *(const ulonglong2*)(wg + k2 * CH + tx * 4);
            unsigned long long bfA = bfp.x, bfB = bfp.y;
            unsigned long long bgA = bgp.x, bgB = bgp.y;
            STEP(0, a0); STEP(1, a1); STEP(2, a2); STEP(3, a3);
        }
    }
#undef STEP

    // ---- epilogue ----
    float* outr = hout + (size_t)seq * SQ * CH;
    float* outs = g_skip + (size_t)seq * SQ * CH;
    float4 rbv = ((const float4*)rb)[tx];
    float4 sbv = ((const float4*)sb)[tx];
    float4 ev  = ((const float4*)es)[tx];

#define EPILOG(ROW, FA_, FB_, GA_, GB_)                                          \
    do {                                                                         \
        int j = j0 + ty4 + (ROW);                                                \
        if (j < L) {                                                             \
            float fx, fy, fz, fw_, gx, gy, gz, gw_;                              \
            UPK2(fx, fy, FA_); UPK2(fz, fw_, FB_);                               \
            UPK2(gx, gy, GA_); UPK2(gz, gw_, GB_);                               \
            float4 hv = ((const float4*)(hp + (size_t)j * CH))[tx];              \
            float4 o;                                                            \
            o.x = fx + rbv.x + hv.x * ev.x;                                      \
            o.y = fy + rbv.y + hv.y * ev.y;                                      \
            o.z = fz + rbv.z + hv.z * ev.z;                                      \
            o.w = fw_ + rbv.w + hv.w * ev.w;                                     \
            float4 s;                                                            \
            s.x = gx + sbv.x; s.y = gy + sbv.y;                                  \
            s.z = gz + sbv.z; s.w = gw_ + sbv.w;                                 \
            if (!skip_init) {                                                    \
                float4 old = ((const float4*)(outs + (size_t)j * CH))[tx];       \
                s.x += old.x; s.y += old.y; s.z += old.z; s.w += old.w;          \
            }                                                                    \
            if (last) {                                                          \
                s.x += o.x; s.y += o.y; s.z += o.z; s.w += o.w;                  \
                ((float4*)(outs + (size_t)j * CH))[tx] = s;                      \
            } else {                                                             \
                ((float4*)(outr + (size_t)j * CH))[tx] = o;                      \
                ((float4*)(outs + (size_t)j * CH))[tx] = s;                      \
            }                                                                    \
        }                                                                        \
    } while (0)

    EPILOG(0, F0A, F0B, G0A, G0B);
    EPILOG(1, F1A, F1B, G1A, G1B);
    EPILOG(2, F2A, F2B, G2A, G2B);
    EPILOG(3, F3A, F3B, G3A, G3B);
#undef EPILOG
}

// ---------------- 5. masked avg/max pool (reads fused res+skip from g_skip) ----------------
__global__ void finalize_kernel() {
    int seq = blockIdx.x;
    int L = g_len[seq];
    int t = threadIdx.x;
    int c = t & 127, half = t >> 7;
    const float* s = g_skip + (size_t)seq * SQ * CH + c;
    float sum = 0.f, mx = -INFINITY;
    for (int j = half; j < L; j += 2) {
        float v = s[(size_t)j * CH];
        sum += v;
        mx = fmaxf(mx, v);
    }
    __shared__ float ssum[256], smx[256];
    ssum[t] = sum; smx[t] = mx;
    __syncthreads();
    if (t < 128) {
        float su = ssum[t] + ssum[t + 128];
        float m = fmaxf(smx[t], smx[t + 128]);
        if (L == 0) m = 0.f;
        float cnt = fmaxf((float)L, 1.f);
        g_feat[seq * 2 * CH + 2 * t]     = su / cnt;
        g_feat[seq * 2 * CH + 2 * t + 1] = m;
    }
}

// ---------------- 6. head MLP ----------------
__global__ void head_kernel(const float* __restrict__ l1w, const float* __restrict__ l1b,
                            const float* __restrict__ l2w, const float* __restrict__ l2b,
                            float* __restrict__ out) {
    int seq = blockIdx.x, t = threadIdx.x;
    __shared__ float fs[256];
    __shared__ float r0[256], r1[256];
    fs[t] = g_feat[seq * 256 + t];
    __syncthreads();
    float o0 = 0.f, o1 = 0.f;
    for (int u = t; u < 1024; u += 256) {
        const float* w = l1w + (size_t)u * 256;
        float a = l1b[u];
#pragma unroll 8
        for (int v = 0; v < 256; v++) a = fmaf(fs[v], w[v], a);
        float hv = fmaxf(a, 0.f);
        o0 = fmaf(hv, l2w[u], o0);
        o1 = fmaf(hv, l2w[1024 + u], o1);
    }
    r0[t] = o0; r1[t] = o1;
    __syncthreads();
    for (int st = 128; st > 0; st >>= 1) {
        if (t < st) { r0[t] += r0[t + st]; r1[t] += r1[t + st]; }
        __syncthreads();
    }
    if (t == 0) {
        out[seq * 2 + 0] = r0[0] + l2b[0];
        out[seq * 2 + 1] = r1[0] + l2b[1];
    }
}

// ---------------- launch ----------------
extern "C" void kernel_launch(void* const* d_in, const int* in_sizes, int n_in,
                              void* d_out, int out_size) {
    const float* raw    = (const float*)d_in[0];
    const int*   labels = (const int*)  d_in[1];
    const float* cv0_w  = (const float*)d_in[2];
    const float* cv0_b  = (const float*)d_in[3];
    const float* se0_w1 = (const float*)d_in[4];
    const float* se0_b1 = (const float*)d_in[5];
    const float* se0_w2 = (const float*)d_in[6];
    const float* se0_b2 = (const float*)d_in[7];
    const float* cv1_w  = (const float*)d_in[8];
    const float* cv1_b  = (const float*)d_in[9];
    const float* se1_w1 = (const float*)d_in[10];
    const float* se1_b1 = (const float*)d_in[11];
    const float* se1_w2 = (const float*)d_in[12];
    const float* se1_b2 = (const float*)d_in[13];
    const float* rs_fw  = (const float*)d_in[14];
    const float* rs_fb  = (const float*)d_in[15];
    const float* rs_gw  = (const float*)d_in[16];
    const float* rs_gb  = (const float*)d_in[17];
    const float* rs_rw  = (const float*)d_in[18];
    const float* rs_rb  = (const float*)d_in[19];
    const float* rs_sw  = (const float*)d_in[20];
    const float* rs_sb  = (const float*)d_in[21];
    const float* l1_w   = (const float*)d_in[22];
    const float* l1_b   = (const float*)d_in[23];
    const float* l2_w   = (const float*)d_in[24];
    const float* l2_b   = (const float*)d_in[25];
    float* out = (float*)d_out;

    gather_kernel<<<NSEQ, 256>>>(raw, labels);
    prep_kernel<<<192, 256>>>(cv1_w, rs_rw, rs_sw);
    cv0_kernel<<<dim3(256, NSEQ), 256>>>(cv0_w, cv0_b);
    semlp_kernel<<<NSEQ, 64>>>(0, se0_w1, se0_b1, se0_w2, se0_b2, 64, 4);
    cv1_kernel<<<dim3(128, NSEQ), 256>>>(cv1_b);
    semlp_kernel<<<NSEQ, 128>>>(1, se1_w1, se1_b1, se1_w2, se1_b2, 128, 8);

    for (int st = 0; st < 3; st++) {
        int flip = st & 1;  // 0: A->B, 1: B->A, 2: A->(fused into g_skip)
        resblock_kernel<<<dim3(128, NSEQ), 256>>>(
            flip,
            rs_fw + (size_t)st * 3 * CH * CH, rs_fb + st * CH,
            rs_gw + (size_t)st * 3 * CH * CH, rs_gb + st * CH,
            rs_rb + st * CH, rs_sb + st * CH,
            st, st == 0, st == 0, st == 2);
    }
    finalize_kernel<<<NSEQ, 256>>>();
    head_kernel<<<NSEQ, 256>>>(l1_w, l1_b, l2_w, l2_b, out);
}